// round 3
// baseline (speedup 1.0000x reference)
#include <cuda_runtime.h>
#include <cstdint>

#define G_EPS 1e-8f

#define BATCH 32768
#define NIN   256
#define NOUT  256
#define NG    5
#define KDIM  (NIN * NG)   // 1280

#define BM 128
#define BN 128
#define BK 40              // 8 inputs * 5 grid points per K tile
#define NKT (KDIM / BK)    // 32

__device__ float g_pmin[256];
__device__ float g_pmax[256];
__device__ float g_st[2];          // s, t for xn = s*x + t
__device__ float g_W[NOUT * KDIM]; // coef * scale, [out][in*5+g]

// ---------------------------------------------------------------------------
// Kernel 1: per-block partial min/max over x
// ---------------------------------------------------------------------------
__global__ void minmax_part_kernel(const float* __restrict__ x, int n4) {
    const float4* x4 = reinterpret_cast<const float4*>(x);
    float mn = 3.402823466e38f, mx = -3.402823466e38f;
    for (int i = blockIdx.x * blockDim.x + threadIdx.x; i < n4;
         i += gridDim.x * blockDim.x) {
        float4 v = x4[i];
        mn = fminf(mn, fminf(fminf(v.x, v.y), fminf(v.z, v.w)));
        mx = fmaxf(mx, fmaxf(fmaxf(v.x, v.y), fmaxf(v.z, v.w)));
    }
#pragma unroll
    for (int o = 16; o > 0; o >>= 1) {
        mn = fminf(mn, __shfl_xor_sync(0xffffffffu, mn, o));
        mx = fmaxf(mx, __shfl_xor_sync(0xffffffffu, mx, o));
    }
    __shared__ float smn[8], smx[8];
    int wid = threadIdx.x >> 5, lane = threadIdx.x & 31;
    if (lane == 0) { smn[wid] = mn; smx[wid] = mx; }
    __syncthreads();
    if (threadIdx.x < 8) {
        mn = smn[threadIdx.x];
        mx = smx[threadIdx.x];
#pragma unroll
        for (int o = 4; o > 0; o >>= 1) {
            mn = fminf(mn, __shfl_xor_sync(0xffu, mn, o));
            mx = fmaxf(mx, __shfl_xor_sync(0xffu, mx, o));
        }
        if (threadIdx.x == 0) {
            g_pmin[blockIdx.x] = mn;
            g_pmax[blockIdx.x] = mx;
        }
    }
}

// ---------------------------------------------------------------------------
// Kernel 2: reduce 256 partials, compute affine normalization constants
// ---------------------------------------------------------------------------
__global__ void minmax_final_kernel() {
    int t = threadIdx.x;  // 256 threads
    float mn = g_pmin[t], mx = g_pmax[t];
#pragma unroll
    for (int o = 16; o > 0; o >>= 1) {
        mn = fminf(mn, __shfl_xor_sync(0xffffffffu, mn, o));
        mx = fmaxf(mx, __shfl_xor_sync(0xffffffffu, mx, o));
    }
    __shared__ float smn[8], smx[8];
    int wid = t >> 5, lane = t & 31;
    if (lane == 0) { smn[wid] = mn; smx[wid] = mx; }
    __syncthreads();
    if (t < 8) {
        mn = smn[t];
        mx = smx[t];
#pragma unroll
        for (int o = 4; o > 0; o >>= 1) {
            mn = fminf(mn, __shfl_xor_sync(0xffu, mn, o));
            mx = fmaxf(mx, __shfl_xor_sync(0xffu, mx, o));
        }
        if (t == 0) {
            float range = mx - mn + G_EPS;
            g_st[0] = 2.0f / range;              // s
            g_st[1] = -2.0f * mn / range - 1.0f; // t
        }
    }
}

// ---------------------------------------------------------------------------
// Kernel 3: fold scale into coef:  g_W[o][i*5+g] = coef[o][i][g] * scale[o][i]
// ---------------------------------------------------------------------------
__global__ void wprep_kernel(const float* __restrict__ coef,
                             const float* __restrict__ scale) {
    int idx = blockIdx.x * blockDim.x + threadIdx.x;
    if (idx < NOUT * KDIM) {
        int o   = idx / KDIM;
        int rem = idx - o * KDIM;
        int i   = rem / NG;
        g_W[idx] = coef[idx] * scale[o * NIN + i];
    }
}

// ---------------------------------------------------------------------------
// Kernel 4: fused basis + GEMM.  out[b][o] = sum_k basis[b][k] * W[o][k] + bias
// Tiling: BM=128 x BN=128 x BK=40, 256 threads, 8x8 outputs per thread.
// Inner product uses packed fma.rn.f32x2 (2 fp32 FMA per instruction).
// ---------------------------------------------------------------------------
__global__ void __launch_bounds__(256, 2)
kan_main_kernel(const float* __restrict__ x, const float* __restrict__ grid,
                const float* __restrict__ bias, float* __restrict__ out) {
    __shared__ float As[BK][132];  // [k][row], stride 132: halves 16 banks apart
    __shared__ float Bs[BK][132];  // [k][col]

    const int t  = threadIdx.x;
    const int tx = t & 15;   // 16 col groups
    const int ty = t >> 4;   // 16 row groups
    const int rowBase = blockIdx.x * BM;
    const int n0      = blockIdx.y * BN;

    const float s   = g_st[0];
    const float tsh = g_st[1];
    float gr[NG];
#pragma unroll
    for (int g = 0; g < NG; g++) gr[g] = grid[g];

    unsigned long long acc[8][4];
#pragma unroll
    for (int r = 0; r < 8; r++)
#pragma unroll
        for (int j = 0; j < 4; j++) acc[r][j] = 0ull;

    // A-fill mapping: each thread owns 4 consecutive inputs of one row
    const int arow  = t >> 1;      // 0..127
    const int ahalf = t & 1;       // which 4-input half of the 8-input tile
    const float* xptr = x + (size_t)(rowBase + arow) * NIN + ahalf * 4;

    // B-fill mapping: each thread owns 20 consecutive k of one output column
    const int bn  = t >> 1;        // 0..127 (local col)
    const int bkh = t & 1;         // which 20-k half
    const float* wbase = g_W + (size_t)(n0 + bn) * KDIM + bkh * 20;

    for (int kt = 0; kt < NKT; kt++) {
        // ---- global loads for this tile ----
        float4 xv = *reinterpret_cast<const float4*>(xptr + kt * 8);
        float4 wv[5];
        const float4* wp = reinterpret_cast<const float4*>(wbase + kt * BK);
#pragma unroll
        for (int q = 0; q < 5; q++) wv[q] = wp[q];

        // ---- basis for 4 x values (register-only, overlaps barrier wait) ----
        float xe[4] = {xv.x, xv.y, xv.z, xv.w};
        float bas[4][NG];
#pragma unroll
        for (int c = 0; c < 4; c++) {
            float xn = fmaf(xe[c], s, tsh);
            float bsum = 0.0f;
#pragma unroll
            for (int g = 0; g < NG; g++) {
                float d = fabsf(xn - gr[g]);
                float b = (d < 1.0f) ? fmaf(-d * d, d, 1.0f) : 0.0f;
                bas[c][g] = b;
                bsum += b;
            }
            float inv = __fdividef(1.0f, bsum + G_EPS);
#pragma unroll
            for (int g = 0; g < NG; g++) bas[c][g] *= inv;
        }

        __syncthreads();  // previous tile's compute done

        // ---- store B tile ----
#pragma unroll
        for (int q = 0; q < 5; q++) {
            int kk = bkh * 20 + q * 4;
            Bs[kk + 0][bn] = wv[q].x;
            Bs[kk + 1][bn] = wv[q].y;
            Bs[kk + 2][bn] = wv[q].z;
            Bs[kk + 3][bn] = wv[q].w;
        }
        // ---- store A tile ----
#pragma unroll
        for (int c = 0; c < 4; c++)
#pragma unroll
            for (int g = 0; g < NG; g++)
                As[(ahalf * 4 + c) * NG + g][arow] = bas[c][g];

        __syncthreads();

        // ---- 8x8 micro-tile inner product, packed f32x2 FMA ----
#pragma unroll
        for (int k = 0; k < BK; k++) {
            unsigned long long bp[4];
#pragma unroll
            for (int j = 0; j < 4; j++)
                bp[j] = *reinterpret_cast<const unsigned long long*>(
                    &Bs[k][2 * (tx + 16 * j)]);
#pragma unroll
            for (int r = 0; r < 8; r++) {
                float av = As[k][ty * 8 + r];
                unsigned long long ap;
                asm("mov.b64 %0, {%1, %1};" : "=l"(ap)
                    : "r"(__float_as_uint(av)));
#pragma unroll
                for (int j = 0; j < 4; j++)
                    asm("fma.rn.f32x2 %0, %1, %2, %0;"
                        : "+l"(acc[r][j])
                        : "l"(ap), "l"(bp[j]));
            }
        }
    }

    // ---- epilogue: unpack pairs, add bias, store ----
#pragma unroll
    for (int r = 0; r < 8; r++) {
        int gm = rowBase + ty * 8 + r;
        float* op = out + (size_t)gm * NOUT + n0;
#pragma unroll
        for (int j = 0; j < 4; j++) {
            unsigned int lo, hi;
            asm("mov.b64 {%0, %1}, %2;" : "=r"(lo), "=r"(hi) : "l"(acc[r][j]));
            int nc = 2 * (tx + 16 * j);
            float2 bv = *reinterpret_cast<const float2*>(bias + n0 + nc);
            float2 v;
            v.x = __uint_as_float(lo) + bv.x;
            v.y = __uint_as_float(hi) + bv.y;
            *reinterpret_cast<float2*>(op + nc) = v;
        }
    }
}

// ---------------------------------------------------------------------------
extern "C" void kernel_launch(void* const* d_in, const int* in_sizes, int n_in,
                              void* d_out, int out_size) {
    const float* x     = (const float*)d_in[0];
    const float* grid  = (const float*)d_in[1];
    const float* coef  = (const float*)d_in[2];
    const float* scale = (const float*)d_in[3];
    const float* bias  = (const float*)d_in[4];
    float* out = (float*)d_out;

    int n = in_sizes[0];  // 32768*256
    minmax_part_kernel<<<256, 256>>>(x, n / 4);
    minmax_final_kernel<<<1, 256>>>();
    wprep_kernel<<<(NOUT * KDIM + 255) / 256, 256>>>(coef, scale);

    dim3 g(BATCH / BM, NOUT / BN);
    kan_main_kernel<<<g, 256>>>(x, grid, bias, out);
}

// round 5
// speedup vs baseline: 3.2757x; 3.2757x over previous
#include <cuda_runtime.h>
#include <cuda_bf16.h>
#include <cstdint>

#define G_EPS 1e-8f

#define BATCH 32768
#define NIN   256
#define NOUT  256
#define NG    5
#define KDIM  (NIN * NG)      // 1280

#define KT_W  64              // K columns per tile (64 bf16 = 128B SW128 row)
#define NT    (KDIM / KT_W)   // 20 K-tiles
#define BM    128             // M rows per CTA

// SMEM stage layout (bytes, within one stage)
#define OFF_AH 0
#define OFF_AL 16384
#define OFF_BH 32768
#define OFF_BL 65536
#define STAGE  98304
#define SM_DATA 1024
#define SMEM_TOTAL (SM_DATA + 2 * STAGE)   // 197632

// idesc for kind::f16, bf16 x bf16 -> f32, M=128, N=256
#define MMA_IDESC 0x8400490u

__device__ float g_pmin[256];
__device__ float g_pmax[256];
__device__ float g_st[2];   // s, t for xn = s*x + t
__device__ __align__(16) __nv_bfloat16 g_Wh[NOUT * KDIM];
__device__ __align__(16) __nv_bfloat16 g_Wl[NOUT * KDIM];

// ---------------------------------------------------------------------------
// Generic helpers
// ---------------------------------------------------------------------------
__device__ __forceinline__ uint32_t smem_u32(const void* p) {
    uint32_t a;
    asm("{ .reg .u64 t; cvta.to.shared.u64 t, %1; cvt.u32.u64 %0, t; }"
        : "=r"(a) : "l"(p));
    return a;
}

// ---------------------------------------------------------------------------
// tcgen05 helpers — only in an sm_103a device pass
// ---------------------------------------------------------------------------
#if defined(__CUDA_ARCH_FEAT_SM103_ALL)
__device__ __forceinline__ uint32_t elect_one() {
    uint32_t pred;
    asm volatile("{\n\t.reg .pred p;\n\telect.sync _|p, 0xFFFFFFFF;\n\t"
                 "selp.b32 %0, 1, 0, p;\n\t}" : "=r"(pred));
    return pred;
}
#define MBAR_INIT(a, n) \
    asm volatile("mbarrier.init.shared.b64 [%0], %1;" :: "r"(a), "r"(n) : "memory")
#define MBAR_WAIT(a, ph) do {                                                     \
    uint32_t _m = (a); uint32_t _p = (ph); uint32_t _d;                           \
    asm volatile("{\n\t.reg .pred p;\n\t"                                         \
        "mbarrier.try_wait.parity.acquire.cta.shared::cta.b64 p, [%1], %2;\n\t"   \
        "selp.b32 %0, 1, 0, p;\n\t}" : "=r"(_d) : "r"(_m), "r"(_p) : "memory");   \
    if (!_d) {                                                                    \
        asm volatile("{\n\t.reg .pred P1;\n\tWL_%=:\n\t"                          \
            "mbarrier.try_wait.parity.acquire.cta.shared::cta.b64 P1, [%0], %1, 0x989680;\n\t" \
            "@P1 bra.uni WD_%=;\n\tbra.uni WL_%=;\n\tWD_%=:\n\t}"                 \
            :: "r"(_m), "r"(_p) : "memory");                                      \
    } } while (0)

static constexpr uint64_t DESC_BASE_SW128 =
    (uint64_t(2) << 61) | (uint64_t(1) << 46) | (uint64_t(64) << 32) |
    (uint64_t(1) << 16);
#define MK_DESC(addr) (DESC_BASE_SW128 | ((uint64_t)((addr) >> 4) & 0x3FFF))

__device__ __forceinline__ void mma_f16_ss(uint32_t d, uint64_t ad, uint64_t bd,
                                           uint32_t idesc, bool acc) {
    uint32_t en = acc ? 1u : 0u;
    asm volatile(
        "{\n\t.reg .pred p;\n\tsetp.ne.u32 p, %5, 0;\n\t"
        "tcgen05.mma.cta_group::1.kind::f16 [%0], %1, %2, %3, {%4, %4, %4, %4}, p;\n\t}"
        :: "r"(d), "l"(ad), "l"(bd), "r"(idesc), "r"(0u), "r"(en) : "memory");
}
#define TC_COMMIT(a)                                                              \
    asm volatile("tcgen05.commit.cta_group::1.mbarrier::arrive::one.shared::cluster.b64 [%0];" \
                 :: "r"(a) : "memory")
#define TC_ALLOC(sa, n)                                                           \
    asm volatile("tcgen05.alloc.cta_group::1.sync.aligned.shared::cta.b32 [%0], %1;" \
                 :: "r"(sa), "r"(n) : "memory")
#define TC_DEALLOC(t, n)                                                          \
    asm volatile("tcgen05.dealloc.cta_group::1.sync.aligned.b32 %0, %1;" :: "r"(t), "r"(n))
#define TC_FENCE_AFTER()  asm volatile("tcgen05.fence::after_thread_sync;" ::: "memory")
#define TC_FENCE_BEFORE() asm volatile("tcgen05.fence::before_thread_sync;" ::: "memory")
#define TC_WAIT_LD()      asm volatile("tcgen05.wait::ld.sync.aligned;" ::: "memory")
#define LDTM_X32(r, a)                                                            \
    asm volatile("tcgen05.ld.sync.aligned.32x32b.x32.b32 "                        \
        "{%0, %1, %2, %3, %4, %5, %6, %7, %8, %9, %10, %11, %12, %13, %14, %15, " \
        " %16, %17, %18, %19, %20, %21, %22, %23, %24, %25, %26, %27, %28, %29, %30, %31}, [%32];" \
        : "=r"((r)[0]),  "=r"((r)[1]),  "=r"((r)[2]),  "=r"((r)[3]),              \
          "=r"((r)[4]),  "=r"((r)[5]),  "=r"((r)[6]),  "=r"((r)[7]),              \
          "=r"((r)[8]),  "=r"((r)[9]),  "=r"((r)[10]), "=r"((r)[11]),             \
          "=r"((r)[12]), "=r"((r)[13]), "=r"((r)[14]), "=r"((r)[15]),             \
          "=r"((r)[16]), "=r"((r)[17]), "=r"((r)[18]), "=r"((r)[19]),             \
          "=r"((r)[20]), "=r"((r)[21]), "=r"((r)[22]), "=r"((r)[23]),             \
          "=r"((r)[24]), "=r"((r)[25]), "=r"((r)[26]), "=r"((r)[27]),             \
          "=r"((r)[28]), "=r"((r)[29]), "=r"((r)[30]), "=r"((r)[31])              \
        : "r"(a))
#endif  // __CUDA_ARCH_FEAT_SM103_ALL

// ---------------------------------------------------------------------------
// Legacy mma.sync helpers (baseline PTX, compiles on plain sm_103)
// ---------------------------------------------------------------------------
__device__ __forceinline__ void ldsm_x4(uint32_t* r, uint32_t addr) {
    asm volatile("ldmatrix.sync.aligned.m8n8.x4.shared.b16 {%0,%1,%2,%3}, [%4];"
                 : "=r"(r[0]), "=r"(r[1]), "=r"(r[2]), "=r"(r[3]) : "r"(addr));
}
__device__ __forceinline__ void ldsm_x2(uint32_t* r, uint32_t addr) {
    asm volatile("ldmatrix.sync.aligned.m8n8.x2.shared.b16 {%0,%1}, [%2];"
                 : "=r"(r[0]), "=r"(r[1]) : "r"(addr));
}
__device__ __forceinline__ void mma_16816(float* d, const uint32_t* a,
                                          const uint32_t* b) {
    asm volatile(
        "mma.sync.aligned.m16n8k16.row.col.f32.bf16.bf16.f32 "
        "{%0,%1,%2,%3}, {%4,%5,%6,%7}, {%8,%9}, {%0,%1,%2,%3};"
        : "+f"(d[0]), "+f"(d[1]), "+f"(d[2]), "+f"(d[3])
        : "r"(a[0]), "r"(a[1]), "r"(a[2]), "r"(a[3]), "r"(b[0]), "r"(b[1]));
}

// ---------------------------------------------------------------------------
// Kernel 1/2: global min/max reduction
// ---------------------------------------------------------------------------
__global__ void minmax_part_kernel(const float* __restrict__ x, int n4) {
    const float4* x4 = reinterpret_cast<const float4*>(x);
    float mn = 3.402823466e38f, mx = -3.402823466e38f;
    for (int i = blockIdx.x * blockDim.x + threadIdx.x; i < n4;
         i += gridDim.x * blockDim.x) {
        float4 v = x4[i];
        mn = fminf(mn, fminf(fminf(v.x, v.y), fminf(v.z, v.w)));
        mx = fmaxf(mx, fmaxf(fmaxf(v.x, v.y), fmaxf(v.z, v.w)));
    }
#pragma unroll
    for (int o = 16; o > 0; o >>= 1) {
        mn = fminf(mn, __shfl_xor_sync(0xffffffffu, mn, o));
        mx = fmaxf(mx, __shfl_xor_sync(0xffffffffu, mx, o));
    }
    __shared__ float smn[8], smx[8];
    int wid = threadIdx.x >> 5, lane = threadIdx.x & 31;
    if (lane == 0) { smn[wid] = mn; smx[wid] = mx; }
    __syncthreads();
    if (threadIdx.x < 8) {
        mn = smn[threadIdx.x];
        mx = smx[threadIdx.x];
#pragma unroll
        for (int o = 4; o > 0; o >>= 1) {
            mn = fminf(mn, __shfl_xor_sync(0xffu, mn, o));
            mx = fmaxf(mx, __shfl_xor_sync(0xffu, mx, o));
        }
        if (threadIdx.x == 0) { g_pmin[blockIdx.x] = mn; g_pmax[blockIdx.x] = mx; }
    }
}

__global__ void minmax_final_kernel() {
    int t = threadIdx.x;
    float mn = g_pmin[t], mx = g_pmax[t];
#pragma unroll
    for (int o = 16; o > 0; o >>= 1) {
        mn = fminf(mn, __shfl_xor_sync(0xffffffffu, mn, o));
        mx = fmaxf(mx, __shfl_xor_sync(0xffffffffu, mx, o));
    }
    __shared__ float smn[8], smx[8];
    int wid = t >> 5, lane = t & 31;
    if (lane == 0) { smn[wid] = mn; smx[wid] = mx; }
    __syncthreads();
    if (t < 8) {
        mn = smn[t];
        mx = smx[t];
#pragma unroll
        for (int o = 4; o > 0; o >>= 1) {
            mn = fminf(mn, __shfl_xor_sync(0xffu, mn, o));
            mx = fmaxf(mx, __shfl_xor_sync(0xffu, mx, o));
        }
        if (t == 0) {
            float range = mx - mn + G_EPS;
            g_st[0] = 2.0f / range;
            g_st[1] = -2.0f * mn / range - 1.0f;
        }
    }
}

// ---------------------------------------------------------------------------
// Kernel 3: W = coef*scale, split into bf16 hi/lo
// ---------------------------------------------------------------------------
__global__ void wprep_kernel(const float* __restrict__ coef,
                             const float* __restrict__ scale) {
    int idx = blockIdx.x * blockDim.x + threadIdx.x;
    if (idx < NOUT * KDIM) {
        int o   = idx / KDIM;
        int rem = idx - o * KDIM;
        int i   = rem / NG;
        float w = coef[idx] * scale[o * NIN + i];
        __nv_bfloat16 wh = __float2bfloat16_rn(w);
        float res = w - __bfloat162float(wh);
        g_Wh[idx] = wh;
        g_Wl[idx] = __float2bfloat16_rn(res);
    }
}

// ---------------------------------------------------------------------------
// A-tile generation: 32 consecutive K columns of one row, phase P0 = kstart%5
// ---------------------------------------------------------------------------
template <int P0>
__device__ __forceinline__ void gen_span(const float* __restrict__ xr, int i0,
                                         float s, float tt,
                                         float g0, float g1, float g2,
                                         float g3, float g4,
                                         char* tAh, char* tAl, int rowbyte) {
    float v0 = 0.f, v1 = 0.f, v2 = 0.f, v3 = 0.f, v4 = 0.f;
    int i = i0;
#pragma unroll
    for (int q = 0; q < 4; q++) {
        uint32_t hp[4], lp[4];
#pragma unroll
        for (int u = 0; u < 4; u++) {
            unsigned short hh[2], ll[2];
#pragma unroll
            for (int e = 0; e < 2; e++) {
                const int j = q * 8 + u * 2 + e;
                const int g = (P0 + j) % 5;
                if (g == 0 || j == 0) {
                    if (g == 0 && j > 0) i++;
                    float xv = __ldg(xr + i);
                    float xn = fmaf(xv, s, tt);
                    float d;
                    d = fabsf(xn - g0); v0 = fmaxf(fmaf(-d * d, d, 1.0f), 0.0f);
                    d = fabsf(xn - g1); v1 = fmaxf(fmaf(-d * d, d, 1.0f), 0.0f);
                    d = fabsf(xn - g2); v2 = fmaxf(fmaf(-d * d, d, 1.0f), 0.0f);
                    d = fabsf(xn - g3); v3 = fmaxf(fmaf(-d * d, d, 1.0f), 0.0f);
                    d = fabsf(xn - g4); v4 = fmaxf(fmaf(-d * d, d, 1.0f), 0.0f);
                    float inv = __fdividef(1.0f, v0 + v1 + v2 + v3 + v4 + G_EPS);
                    v0 *= inv; v1 *= inv; v2 *= inv; v3 *= inv; v4 *= inv;
                }
                float v = (g == 0) ? v0 : (g == 1) ? v1 : (g == 2) ? v2
                                        : (g == 3) ? v3 : v4;
                __nv_bfloat16 bh = __float2bfloat16_rn(v);
                float rem = v - __bfloat162float(bh);
                __nv_bfloat16 bl = __float2bfloat16_rn(rem);
                hh[e] = __bfloat16_as_ushort(bh);
                ll[e] = __bfloat16_as_ushort(bl);
            }
            hp[u] = (uint32_t)hh[0] | ((uint32_t)hh[1] << 16);
            lp[u] = (uint32_t)ll[0] | ((uint32_t)ll[1] << 16);
        }
        int off = rowbyte + q * 16;
        int sw  = off ^ ((off >> 3) & 0x70);
        *reinterpret_cast<uint4*>(tAh + sw) = make_uint4(hp[0], hp[1], hp[2], hp[3]);
        *reinterpret_cast<uint4*>(tAl + sw) = make_uint4(lp[0], lp[1], lp[2], lp[3]);
    }
}

// Shared producers: fill one stage (Ah/Al/Bh/Bl, SW128 swizzled)
__device__ __forceinline__ void produce_B(char* stage, int kt, int t) {
    const char* wh = reinterpret_cast<const char*>(g_Wh) + kt * 128;
    const char* wl = reinterpret_cast<const char*>(g_Wl) + kt * 128;
#pragma unroll
    for (int z = 0; z < 8; z++) {
        int c   = t + z * 256;
        int n   = c >> 3;
        int k16 = c & 7;
        size_t gb = (size_t)n * (KDIM * 2) + k16 * 16;
        uint4 vh = *reinterpret_cast<const uint4*>(wh + gb);
        uint4 vl = *reinterpret_cast<const uint4*>(wl + gb);
        int off = n * 128 + k16 * 16;
        int sw  = off ^ ((off >> 3) & 0x70);
        *reinterpret_cast<uint4*>(stage + OFF_BH + sw) = vh;
        *reinterpret_cast<uint4*>(stage + OFF_BL + sw) = vl;
    }
}

__device__ __forceinline__ void produce_A(char* stage, int kt, int half,
                                          int rowbyte,
                                          const float* __restrict__ xr,
                                          float s, float tt,
                                          float g0, float g1, float g2,
                                          float g3, float g4) {
    int ks = kt * KT_W + half * 32;
    int i0 = ks / 5;
    switch (ks % 5) {
    case 0: gen_span<0>(xr, i0, s, tt, g0, g1, g2, g3, g4,
                        stage + OFF_AH, stage + OFF_AL, rowbyte); break;
    case 1: gen_span<1>(xr, i0, s, tt, g0, g1, g2, g3, g4,
                        stage + OFF_AH, stage + OFF_AL, rowbyte); break;
    case 2: gen_span<2>(xr, i0, s, tt, g0, g1, g2, g3, g4,
                        stage + OFF_AH, stage + OFF_AL, rowbyte); break;
    case 3: gen_span<3>(xr, i0, s, tt, g0, g1, g2, g3, g4,
                        stage + OFF_AH, stage + OFF_AL, rowbyte); break;
    default: gen_span<4>(xr, i0, s, tt, g0, g1, g2, g3, g4,
                         stage + OFF_AH, stage + OFF_AL, rowbyte); break;
    }
}

// ---------------------------------------------------------------------------
// Main kernel: per-CTA 128x256 GEMM over K=1280 (20 tiles of 64),
// 3 bf16 split passes.  tcgen05 path if available, mma.sync fallback else.
// ---------------------------------------------------------------------------
__global__ void __launch_bounds__(256, 1)
kan_mma_kernel(const float* __restrict__ x, const float* __restrict__ grid,
               const float* __restrict__ bias, float* __restrict__ out) {
    extern __shared__ char dsm[];
    const uint32_t sb = smem_u32(dsm);
    const int t = threadIdx.x;
    const int rowBase = blockIdx.x * BM;

    const float s  = g_st[0];
    const float tt = g_st[1];
    const float gr0 = __ldg(grid + 0), gr1 = __ldg(grid + 1),
                gr2 = __ldg(grid + 2), gr3 = __ldg(grid + 3),
                gr4 = __ldg(grid + 4);

    const int r    = t & 127;     // A row this thread produces
    const int half = t >> 7;      // which 32-col half of the 64-col tile
    const int rowbyte = r * 128 + half * 64;
    const float* xr = x + (size_t)(rowBase + r) * NIN;

#if defined(__CUDA_ARCH_FEAT_SM103_ALL)
    // ===================== tcgen05 path =====================
    if ((t >> 5) == 0) TC_ALLOC(sb + 0, 512);
    if (t == 0) { MBAR_INIT(sb + 8, 1); MBAR_INIT(sb + 16, 1); }
    __syncthreads();
    uint32_t tmem;
    asm volatile("ld.shared.b32 %0, [%1];" : "=r"(tmem) : "r"(sb + 0));

    int ph0 = 0, ph1 = 0;

    for (int kt = 0; kt < NT; kt++) {
        const int b = kt & 1;
        if (kt >= 2) {
            if (b == 0) { MBAR_WAIT(sb + 8, ph0);  ph0 ^= 1; }
            else        { MBAR_WAIT(sb + 16, ph1); ph1 ^= 1; }
        }
        char* stage = dsm + SM_DATA + b * STAGE;

        produce_B(stage, kt, t);
        produce_A(stage, kt, half, rowbyte, xr, s, tt, gr0, gr1, gr2, gr3, gr4);

        asm volatile("fence.proxy.async.shared::cta;" ::: "memory");
        __syncthreads();

        if ((t >> 5) == 0) {
            if (elect_one()) {
                uint32_t base = sb + SM_DATA + b * STAGE;
                uint64_t dah = MK_DESC(base + OFF_AH);
                uint64_t dal = MK_DESC(base + OFF_AL);
                uint64_t dbh = MK_DESC(base + OFF_BH);
                uint64_t dbl = MK_DESC(base + OFF_BL);
#pragma unroll
                for (int st = 0; st < 4; st++)
                    mma_f16_ss(tmem, dah + st * 2, dbh + st * 2, MMA_IDESC,
                               !(kt == 0 && st == 0));
#pragma unroll
                for (int st = 0; st < 4; st++)
                    mma_f16_ss(tmem, dal + st * 2, dbh + st * 2, MMA_IDESC, true);
#pragma unroll
                for (int st = 0; st < 4; st++)
                    mma_f16_ss(tmem, dah + st * 2, dbl + st * 2, MMA_IDESC, true);
                TC_COMMIT(sb + 8 + 8 * b);
            }
        }
    }

    MBAR_WAIT(sb + 16, ph1);
    TC_FENCE_AFTER();

    {
        int w = t >> 5, lane = t & 31;
        int sp = w & 3, ch = w >> 2;
        int row = rowBase + sp * 32 + lane;
        float* orow = out + (size_t)row * NOUT;
#pragma unroll
        for (int cc = 0; cc < 4; cc++) {
            int c0 = ch * 128 + cc * 32;
            uint32_t dr[32];
            LDTM_X32(dr, tmem + c0);
            TC_WAIT_LD();
#pragma unroll
            for (int c4 = 0; c4 < 8; c4++) {
                float4 bv = *reinterpret_cast<const float4*>(bias + c0 + c4 * 4);
                float4 v;
                v.x = __uint_as_float(dr[c4 * 4 + 0]) + bv.x;
                v.y = __uint_as_float(dr[c4 * 4 + 1]) + bv.y;
                v.z = __uint_as_float(dr[c4 * 4 + 2]) + bv.z;
                v.w = __uint_as_float(dr[c4 * 4 + 3]) + bv.w;
                *reinterpret_cast<float4*>(orow + c0 + c4 * 4) = v;
            }
        }
    }
    TC_FENCE_BEFORE();
    __syncthreads();
    if (t == 0) {
        asm volatile("mbarrier.inval.shared.b64 [%0];" :: "r"(sb + 8) : "memory");
        asm volatile("mbarrier.inval.shared.b64 [%0];" :: "r"(sb + 16) : "memory");
    }
    __syncthreads();
    if ((t >> 5) == 0) TC_DEALLOC(tmem, 512);

#else
    // ===================== mma.sync fallback (plain sm_103) =====================
    const int w = t >> 5, lane = t & 31;
    const int m0 = w * 16;  // 16 M-rows per warp

    float acc[32][4];
#pragma unroll
    for (int nb = 0; nb < 32; nb++)
#pragma unroll
        for (int j = 0; j < 4; j++) acc[nb][j] = 0.0f;

    // Per-lane ldmatrix address components (swizzle commutes with +nb*1024)
    const int a_row = m0 + (lane & 15);
    const int a_kb0 = (lane >> 4) * 16;
    const int b_n7  = lane & 7;
    const int b_kb0 = ((lane >> 3) & 1) * 16;

    char* stage = dsm + SM_DATA;   // single stage

    for (int kt = 0; kt < NT; kt++) {
        produce_B(stage, kt, t);
        produce_A(stage, kt, half, rowbyte, xr, s, tt, gr0, gr1, gr2, gr3, gr4);
        __syncthreads();

#pragma unroll
        for (int ks = 0; ks < 4; ks++) {
            int aoff = a_row * 128 + ks * 32 + a_kb0;
            int asw  = aoff ^ ((aoff >> 3) & 0x70);
            uint32_t ah[4], al[4];
            ldsm_x4(ah, sb + SM_DATA + OFF_AH + asw);
            ldsm_x4(al, sb + SM_DATA + OFF_AL + asw);

            int boff = b_n7 * 128 + ks * 32 + b_kb0;
            int bsw  = boff ^ ((boff >> 3) & 0x70);
            uint32_t bhA = sb + SM_DATA + OFF_BH + bsw;
            uint32_t blA = sb + SM_DATA + OFF_BL + bsw;
#pragma unroll
            for (int nb = 0; nb < 32; nb++) {
                uint32_t bh[2], bl[2];
                ldsm_x2(bh, bhA + nb * 1024);
                ldsm_x2(bl, blA + nb * 1024);
                mma_16816(acc[nb], ah, bh);
                mma_16816(acc[nb], al, bh);
                mma_16816(acc[nb], ah, bl);
            }
        }
        __syncthreads();
    }

    // Epilogue: thread t of warp w holds rows m0 + lane/4 (+8), cols nb*8 + 2*(lane%4)
    {
        const int er = lane >> 2;
        const int ec = (lane & 3) * 2;
        const size_t row0 = (size_t)(rowBase + m0 + er);
#pragma unroll
        for (int nb = 0; nb < 32; nb++) {
            int c = nb * 8 + ec;
            float2 b2 = *reinterpret_cast<const float2*>(bias + c);
            float2 v0, v1;
            v0.x = acc[nb][0] + b2.x;
            v0.y = acc[nb][1] + b2.y;
            v1.x = acc[nb][2] + b2.x;
            v1.y = acc[nb][3] + b2.y;
            *reinterpret_cast<float2*>(out + row0 * NOUT + c) = v0;
            *reinterpret_cast<float2*>(out + (row0 + 8) * NOUT + c) = v1;
        }
    }
#endif
}

// ---------------------------------------------------------------------------
extern "C" void kernel_launch(void* const* d_in, const int* in_sizes, int n_in,
                              void* d_out, int out_size) {
    const float* x     = (const float*)d_in[0];
    const float* grid  = (const float*)d_in[1];
    const float* coef  = (const float*)d_in[2];
    const float* scale = (const float*)d_in[3];
    const float* bias  = (const float*)d_in[4];
    float* out = (float*)d_out;

    int n = in_sizes[0];
    minmax_part_kernel<<<256, 256>>>(x, n / 4);
    minmax_final_kernel<<<1, 256>>>();
    wprep_kernel<<<(NOUT * KDIM + 255) / 256, 256>>>(coef, scale);

    cudaFuncSetAttribute(kan_mma_kernel,
                         cudaFuncAttributeMaxDynamicSharedMemorySize,
                         SMEM_TOTAL);
    kan_mma_kernel<<<BATCH / BM, 256, SMEM_TOTAL>>>(x, grid, bias, out);
}